// round 16
// baseline (speedup 1.0000x reference)
#include <cuda_runtime.h>
#include <cuda_fp16.h>
#include <math.h>
#include <stdint.h>

#define D_MODEL 1024
#define NHEAD   16
#define DH      64
#define BATCH   2
#define SEQ     2048
#define MROWS   (BATCH*SEQ)   // 4096
#define BHN     (BATCH*NHEAD) // 32

// Scratch (allocation-free): fp16 buffers.
__device__ __align__(16) __half g_Qh[BHN * SEQ * DH];
__device__ __align__(16) __half g_Kh[BHN * SEQ * DH];
__device__ __align__(16) __half g_Vh[BHN * SEQ * DH];
__device__ __align__(16) __half g_Oh[BHN * SEQ * DH];
__device__ __align__(16) __half g_xh[MROWS * D_MODEL];
__device__ __align__(16) __half g_Wt[4][D_MODEL * D_MODEL];  // [n][k] fp16

// ---------------------------------------------------------------------------
// helpers
// ---------------------------------------------------------------------------
__device__ __forceinline__ uint32_t pack2(float a, float b) {
    __half2 h = __floats2half2_rn(a, b);
    return *reinterpret_cast<uint32_t*>(&h);
}
__device__ __forceinline__ uint32_t h2exp2(uint32_t x) {
    uint32_t r;
    asm volatile("ex2.approx.f16x2 %0, %1;" : "=r"(r) : "r"(x));
    return r;
}
__device__ __forceinline__ uint32_t smem_u32(const void* p) {
    uint32_t r;
    asm("{ .reg .u64 t; cvta.to.shared.u64 t, %1; cvt.u32.u64 %0, t; }"
        : "=r"(r) : "l"(p));
    return r;
}
__device__ __forceinline__ void mma16(float* c, const uint32_t* a,
                                      uint32_t b0, uint32_t b1) {
    asm volatile(
        "mma.sync.aligned.m16n8k16.row.col.f32.f16.f16.f32 "
        "{%0,%1,%2,%3}, {%4,%5,%6,%7}, {%8,%9}, {%0,%1,%2,%3};"
        : "+f"(c[0]), "+f"(c[1]), "+f"(c[2]), "+f"(c[3])
        : "r"(a[0]), "r"(a[1]), "r"(a[2]), "r"(a[3]), "r"(b0), "r"(b1));
}
__device__ __forceinline__ void ldm_x4(uint32_t* r, uint32_t addr) {
    asm volatile("ldmatrix.sync.aligned.m8n8.x4.shared.b16 {%0,%1,%2,%3}, [%4];"
        : "=r"(r[0]), "=r"(r[1]), "=r"(r[2]), "=r"(r[3]) : "r"(addr));
}
__device__ __forceinline__ void ldm_x4_t(uint32_t* r, uint32_t addr) {
    asm volatile("ldmatrix.sync.aligned.m8n8.x4.trans.shared.b16 {%0,%1,%2,%3}, [%4];"
        : "=r"(r[0]), "=r"(r[1]), "=r"(r[2]), "=r"(r[3]) : "r"(addr));
}
__device__ __forceinline__ void cpa16(uint32_t dst, const void* src) {
    asm volatile("cp.async.cg.shared.global [%0], [%1], 16;"
                 :: "r"(dst), "l"(src) : "memory");
}
#define CPA_COMMIT() asm volatile("cp.async.commit_group;" ::: "memory")
#define CPA_WAIT0()  asm volatile("cp.async.wait_group 0;" ::: "memory")
#define CPA_WAIT1()  asm volatile("cp.async.wait_group 1;" ::: "memory")
#define CPA_WAIT2()  asm volatile("cp.async.wait_group 2;" ::: "memory")

// ---------------------------------------------------------------------------
// Fused pre-pass: z<4 -> W[z] transpose to fp16 [n][k]; z==4 -> x to fp16.
// grid (32, 32, 5), block 256.
// ---------------------------------------------------------------------------
__global__ __launch_bounds__(256) void prepass_kernel(
    const float* __restrict__ x,
    const float* __restrict__ W0, const float* __restrict__ W1,
    const float* __restrict__ W2, const float* __restrict__ W3)
{
    const int z = blockIdx.z;
    if (z == 4) {
        int bid = blockIdx.y * 32 + blockIdx.x;
        #pragma unroll
        for (int j = 0; j < 4; j++) {
            int idx = (bid * 4 + j) * 256 + threadIdx.x;
            float4 v = *(const float4*)(x + (size_t)idx * 4);
            *(uint2*)(g_xh + (size_t)idx * 4) =
                make_uint2(pack2(v.x, v.y), pack2(v.z, v.w));
        }
        return;
    }
    __shared__ float tile[32][33];
    const float* W = (z == 0) ? W0 : (z == 1) ? W1 : (z == 2) ? W2 : W3;
    const int tx = threadIdx.x & 31, ty = threadIdx.x >> 5;  // (32, 8)
    const int k0 = blockIdx.y * 32, n0 = blockIdx.x * 32;
    #pragma unroll
    for (int j = 0; j < 4; j++)
        tile[ty + 8 * j][tx] = W[(size_t)(k0 + ty + 8 * j) * D_MODEL + n0 + tx];
    __syncthreads();
    __half* Wt = g_Wt[z];
    #pragma unroll
    for (int jj = 0; jj < 2; jj++) {
        int w_ = threadIdx.x + 256 * jj;   // 0..511
        int n = w_ >> 4, c = w_ & 15;
        uint32_t u = pack2(tile[2 * c][n], tile[2 * c + 1][n]);
        *(uint32_t*)(Wt + (size_t)(n0 + n) * D_MODEL + k0 + 2 * c) = u;
    }
}

// ---------------------------------------------------------------------------
// GEMM geometry: CTA 128x128, 128 threads (4 warps, 2x2), warp tile 64x64.
// BK=32, 4-stage cp.async pipeline (prefetch distance 3), 2 CTAs/SM.
// Mainloop unrolled x4 so the buffer index (s & 3) is compile-time constant.
// ---------------------------------------------------------------------------
#define BK   32
#define NS   (D_MODEL / BK)        // 32
#define GST  20                     // u32 words per smem row
#define BUFW (256 * GST)            // A(128) + W(128) rows per buffer
#define GEMM_SMEM (4 * BUFW * 4)    // 81920 B dynamic

struct GemmCtx {
    int m0w, n0w;
    int lrow, a_roff, a_coff, b_roff, b_coff;
};
__device__ __forceinline__ void gemm_stage(const GemmCtx& c, uint32_t ab,
                                           float acc[4][8][4]) {
    const uint32_t wb = ab + 128 * GST * 4;
    #pragma unroll
    for (int ks = 0; ks < 2; ks++) {
        const int k0w = ks * 8;
        uint32_t a[4][4], b[4][4];
        #pragma unroll
        for (int mt = 0; mt < 4; mt++)
            ldm_x4(a[mt], ab + ((c.m0w + mt * 16 + c.a_roff + c.lrow) * GST
                                + k0w + c.a_coff) * 4);
        #pragma unroll
        for (int np = 0; np < 4; np++)
            ldm_x4(b[np], wb + ((c.n0w + np * 16 + c.b_roff + c.lrow) * GST
                                + k0w + c.b_coff) * 4);
        #pragma unroll
        for (int nt = 0; nt < 8; nt++) {
            uint32_t b0 = b[nt >> 1][(nt & 1) * 2];
            uint32_t b1 = b[nt >> 1][(nt & 1) * 2 + 1];
            #pragma unroll
            for (int mt = 0; mt < 4; mt++)
                mma16(acc[mt][nt], a[mt], b0, b1);
        }
    }
}

// stage wait ladder: group s must have completed
#define GEMM_WAIT(s) do { \
    if ((s) + 2 < NS) CPA_WAIT2(); \
    else if ((s) + 1 < NS) CPA_WAIT1(); \
    else CPA_WAIT0(); \
} while (0)

// ---------------------------------------------------------------------------
// Fused QKV projection GEMM. grid (8, 32, 3), block 128, 2 CTAs/SM.
// ---------------------------------------------------------------------------
__global__ __launch_bounds__(128, 2) void qkv_gemm_kernel(
    const __half* __restrict__ wt_base,
    const float* __restrict__ bq, const float* __restrict__ bk,
    const float* __restrict__ bv)
{
    extern __shared__ uint32_t sm[];

    const int tid  = threadIdx.x;
    const int w    = tid >> 5, lane = tid & 31;
    const int g    = lane >> 2, t = lane & 3;
    const int bm   = blockIdx.y * 128, bn = blockIdx.x * 128;
    const int bb   = bm >> 11;
    const int z    = blockIdx.z;

    const __half* Wt = wt_base + (size_t)z * D_MODEL * D_MODEL;
    const float* bias = (z == 0) ? bq : (z == 1) ? bk : bv;
    const float alpha = (z == 0) ? 0.125f * 1.4426950408889634f : 1.0f;

    GemmCtx c;
    c.m0w = (w >> 1) * 64; c.n0w = (w & 1) * 64;
    c.lrow = lane & 7;
    c.a_roff = ((lane >> 3) & 1) * 8;
    c.a_coff = (lane >> 4) * 4;
    c.b_roff = (lane >> 4) * 8;
    c.b_coff = ((lane >> 3) & 1) * 4;

    const uint32_t smb = smem_u32(sm);

    auto issue = [&](int kt, int buf) {
        uint32_t dst = smb + buf * (BUFW * 4);
        #pragma unroll
        for (int i = 0; i < 4; i++) {
            int idx = tid + 128 * i;
            int row = idx >> 2, seg = idx & 3;
            cpa16(dst + (row * GST + seg * 4) * 4,
                  g_xh + (size_t)(bm + row) * D_MODEL + kt + seg * 8);
            cpa16(dst + ((128 + row) * GST + seg * 4) * 4,
                  Wt + (size_t)(bn + row) * D_MODEL + kt + seg * 8);
        }
        CPA_COMMIT();
    };

    issue(0, 0);
    issue(BK, 1);
    issue(2 * BK, 2);

    float acc[4][8][4] = {};

    #pragma unroll 4
    for (int s = 0; s < NS; s++) {
        GEMM_WAIT(s);
        __syncthreads();
        if (s + 3 < NS) issue((s + 3) * BK, (s + 3) & 3);
        gemm_stage(c, smb + (s & 3) * (BUFW * 4), acc);
    }

    __half* outp = (z == 0) ? g_Qh : (z == 1) ? g_Kh : g_Vh;
    #pragma unroll
    for (int mt = 0; mt < 4; mt++) {
        #pragma unroll
        for (int nt = 0; nt < 8; nt++) {
            int rl = c.m0w + mt * 16 + g;
            int cl = c.n0w + nt * 8 + t * 2;
            float2 bv2 = *(const float2*)&bias[bn + cl];
            float v00 = (acc[mt][nt][0] + bv2.x) * alpha;
            float v01 = (acc[mt][nt][1] + bv2.y) * alpha;
            float v10 = (acc[mt][nt][2] + bv2.x) * alpha;
            float v11 = (acc[mt][nt][3] + bv2.y) * alpha;
            int col = bn + cl;
            int h = col >> 6, d = col & 63;
            int t0r = (bm + rl) & (SEQ - 1);
            __half* ob = outp + ((size_t)(bb * NHEAD + h)) * SEQ * DH;
            *(uint32_t*)&ob[(size_t)t0r * DH + d] = pack2(v00, v01);
            *(uint32_t*)&ob[(size_t)(t0r + 8) * DH + d] = pack2(v10, v11);
        }
    }
}

// ---------------------------------------------------------------------------
// Output GEMM: d_out = concat(O) @ Wo + bo. grid (8, 32), block 128.
// ---------------------------------------------------------------------------
__global__ __launch_bounds__(128, 2) void out_gemm_kernel(
    const __half* __restrict__ Wt, const float* __restrict__ bias,
    float* __restrict__ Cout)
{
    extern __shared__ uint32_t sm[];

    const int tid  = threadIdx.x;
    const int w    = tid >> 5, lane = tid & 31;
    const int g    = lane >> 2, t = lane & 3;
    const int bm   = blockIdx.y * 128, bn = blockIdx.x * 128;
    const int bb   = bm >> 11;

    GemmCtx c;
    c.m0w = (w >> 1) * 64; c.n0w = (w & 1) * 64;
    c.lrow = lane & 7;
    c.a_roff = ((lane >> 3) & 1) * 8;
    c.a_coff = (lane >> 4) * 4;
    c.b_roff = (lane >> 4) * 8;
    c.b_coff = ((lane >> 3) & 1) * 4;

    const uint32_t smb = smem_u32(sm);

    auto issue = [&](int kt, int buf) {
        uint32_t dst = smb + buf * (BUFW * 4);
        const int h = kt >> 6, d0 = kt & 63;
        #pragma unroll
        for (int i = 0; i < 4; i++) {
            int idx = tid + 128 * i;
            int row = idx >> 2, seg = idx & 3;
            int tt = (bm + row) & (SEQ - 1);
            cpa16(dst + (row * GST + seg * 4) * 4,
                  g_Oh + (((size_t)(bb * NHEAD + h)) * SEQ + tt) * DH
                  + d0 + seg * 8);
            cpa16(dst + ((128 + row) * GST + seg * 4) * 4,
                  Wt + (size_t)(bn + row) * D_MODEL + kt + seg * 8);
        }
        CPA_COMMIT();
    };

    issue(0, 0);
    issue(BK, 1);
    issue(2 * BK, 2);

    float acc[4][8][4] = {};

    #pragma unroll 4
    for (int s = 0; s < NS; s++) {
        GEMM_WAIT(s);
        __syncthreads();
        if (s + 3 < NS) issue((s + 3) * BK, (s + 3) & 3);
        gemm_stage(c, smb + (s & 3) * (BUFW * 4), acc);
    }

    #pragma unroll
    for (int mt = 0; mt < 4; mt++) {
        #pragma unroll
        for (int nt = 0; nt < 8; nt++) {
            int rl = c.m0w + mt * 16 + g;
            int cl = c.n0w + nt * 8 + t * 2;
            float2 bv2 = *(const float2*)&bias[bn + cl];
            *(float2*)&Cout[(size_t)(bm + rl) * D_MODEL + bn + cl] =
                make_float2(acc[mt][nt][0] + bv2.x, acc[mt][nt][1] + bv2.y);
            *(float2*)&Cout[(size_t)(bm + rl + 8) * D_MODEL + bn + cl] =
                make_float2(acc[mt][nt][2] + bv2.x, acc[mt][nt][3] + bv2.y);
        }
    }
}

// ---------------------------------------------------------------------------
// Flash attention (R10 config). Mainloop unrolled x2 so the buffer index
// (it & 1) is compile-time constant in each copy.
// ---------------------------------------------------------------------------
#define FST 36
#define KVW (64 * FST)
#define H2_ONES 0x3C003C00u

__global__ __launch_bounds__(128, 4) void flash_kernel()
{
    __shared__ uint32_t Ks[2][KVW];
    __shared__ uint32_t Vs[2][KVW];

    const int tid = threadIdx.x;
    const int w = tid >> 5, lane = tid & 31;
    const int g = lane >> 2, t = lane & 3;
    const int bh = blockIdx.y;
    const int q0 = blockIdx.x * 64;

    const __half* Qp = g_Qh + ((size_t)bh * SEQ + q0) * DH;
    const __half* Kp = g_Kh + (size_t)bh * SEQ * DH;
    const __half* Vp = g_Vh + (size_t)bh * SEQ * DH;

    const int lr = w * 16 + g;

    uint32_t qf[4][4];
    #pragma unroll
    for (int s = 0; s < 4; s++) {
        qf[s][0] = *(const uint32_t*)(Qp + (size_t)lr * DH + s * 16 + 2 * t);
        qf[s][1] = *(const uint32_t*)(Qp + (size_t)(lr + 8) * DH + s * 16 + 2 * t);
        qf[s][2] = *(const uint32_t*)(Qp + (size_t)lr * DH + s * 16 + 8 + 2 * t);
        qf[s][3] = *(const uint32_t*)(Qp + (size_t)(lr + 8) * DH + s * 16 + 8 + 2 * t);
    }

    const uint32_t ksb = smem_u32(Ks), vsb = smem_u32(Vs);
    const int lrow = lane & 7;
    const uint32_t k_lane = ksb + (lrow * FST + (lane >> 3) * 4) * 4;
    const uint32_t v_lane = vsb + ((((lane >> 3) & 1) * 8 + lrow) * FST
                                   + (lane >> 4) * 4) * 4;

    auto issueKV = [&](int kt, int buf) {
        const uint32_t koff = buf * (KVW * 4);
        #pragma unroll
        for (int i = 0; i < 4; i++) {
            int idx = i * 128 + tid;
            int row = idx >> 3, seg = idx & 7;
            cpa16(ksb + koff + (row * FST + seg * 4) * 4,
                  Kp + (size_t)(kt + row) * DH + seg * 8);
            cpa16(vsb + koff + (row * FST + seg * 4) * 4,
                  Vp + (size_t)(kt + row) * DH + seg * 8);
        }
        CPA_COMMIT();
    };

    issueKV(0, 0);

    float o[8][4] = {};
    float lsum[4] = {};
    float m0 = -INFINITY, m1 = -INFINITY;

    #pragma unroll 2
    for (int it = 0; it < SEQ / 64; it++) {
        const int buf = it & 1;
        CPA_WAIT0();
        __syncthreads();
        if (it + 1 < SEQ / 64) issueKV((it + 1) * 64, buf ^ 1);

        const uint32_t kl = k_lane + buf * (KVW * 4);
        const uint32_t vl = v_lane + buf * (KVW * 4);

        float s_[8][4] = {};
        #pragma unroll
        for (int nt = 0; nt < 8; nt++) {
            uint32_t kb[4], kb2[4];
            uint32_t base = kl + nt * 8 * (FST * 4);
            ldm_x4(kb,  base);
            ldm_x4(kb2, base + 16 * 4);
            mma16(s_[nt], qf[0], kb[0],  kb[1]);
            mma16(s_[nt], qf[1], kb[2],  kb[3]);
            mma16(s_[nt], qf[2], kb2[0], kb2[1]);
            mma16(s_[nt], qf[3], kb2[2], kb2[3]);
        }

        float mx0 = -INFINITY, mx1 = -INFINITY;
        #pragma unroll
        for (int nt = 0; nt < 8; nt++) {
            mx0 = fmaxf(mx0, fmaxf(s_[nt][0], s_[nt][1]));
            mx1 = fmaxf(mx1, fmaxf(s_[nt][2], s_[nt][3]));
        }
        mx0 = fmaxf(mx0, __shfl_xor_sync(0xffffffffu, mx0, 1));
        mx0 = fmaxf(mx0, __shfl_xor_sync(0xffffffffu, mx0, 2));
        mx1 = fmaxf(mx1, __shfl_xor_sync(0xffffffffu, mx1, 1));
        mx1 = fmaxf(mx1, __shfl_xor_sync(0xffffffffu, mx1, 2));

        float mn0 = fmaxf(m0, mx0), mn1 = fmaxf(m1, mx1);
        float c0 = exp2f(m0 - mn0), c1 = exp2f(m1 - mn1);
        m0 = mn0; m1 = mn1;

        uint32_t pf[4][4];
        #pragma unroll
        for (int s = 0; s < 4; s++) {
            pf[s][0] = h2exp2(pack2(s_[2 * s][0] - mn0,     s_[2 * s][1] - mn0));
            pf[s][1] = h2exp2(pack2(s_[2 * s][2] - mn1,     s_[2 * s][3] - mn1));
            pf[s][2] = h2exp2(pack2(s_[2 * s + 1][0] - mn0, s_[2 * s + 1][1] - mn0));
            pf[s][3] = h2exp2(pack2(s_[2 * s + 1][2] - mn1, s_[2 * s + 1][3] - mn1));
        }

        #pragma unroll
        for (int nt = 0; nt < 8; nt++) {
            o[nt][0] *= c0; o[nt][1] *= c0;
            o[nt][2] *= c1; o[nt][3] *= c1;
        }
        lsum[0] *= c0; lsum[1] *= c0; lsum[2] *= c1; lsum[3] *= c1;

        #pragma unroll
        for (int s = 0; s < 4; s++)
            mma16(lsum, pf[s], H2_ONES, H2_ONES);

        #pragma unroll
        for (int s = 0; s < 4; s++) {
            uint32_t base = vl + s * 16 * (FST * 4);
            #pragma unroll
            for (int np = 0; np < 4; np++) {
                uint32_t vb[4];
                ldm_x4_t(vb, base + np * 8 * 4);
                mma16(o[2 * np],     pf[s], vb[0], vb[1]);
                mma16(o[2 * np + 1], pf[s], vb[2], vb[3]);
            }
        }
    }

    float inv0 = 1.0f / lsum[0], inv1 = 1.0f / lsum[2];
    __half* Op = g_Oh + ((size_t)bh * SEQ + q0) * DH;
    #pragma unroll
    for (int nt = 0; nt < 8; nt++) {
        int col = nt * 8 + t * 2;
        *(uint32_t*)&Op[(size_t)lr * DH + col] =
            pack2(o[nt][0] * inv0, o[nt][1] * inv0);
        *(uint32_t*)&Op[(size_t)(lr + 8) * DH + col] =
            pack2(o[nt][2] * inv1, o[nt][3] * inv1);
    }
}

// ---------------------------------------------------------------------------
extern "C" void kernel_launch(void* const* d_in, const int* in_sizes, int n_in,
                              void* d_out, int out_size)
{
    const float* x  = (const float*)d_in[0];
    const float* Wq = (const float*)d_in[1];
    const float* bq = (const float*)d_in[2];
    const float* Wk = (const float*)d_in[3];
    const float* bk = (const float*)d_in[4];
    const float* Wv = (const float*)d_in[5];
    const float* bv = (const float*)d_in[6];
    const float* Wo = (const float*)d_in[7];
    const float* bo = (const float*)d_in[8];
    (void)in_sizes; (void)n_in; (void)out_size;

    static __half* wt_base = nullptr;
    if (!wt_base) {
        void* p = nullptr;
        cudaGetSymbolAddress(&p, g_Wt);
        wt_base = (__half*)p;
        cudaFuncSetAttribute(qkv_gemm_kernel,
            cudaFuncAttributeMaxDynamicSharedMemorySize, GEMM_SMEM);
        cudaFuncSetAttribute(out_gemm_kernel,
            cudaFuncAttributeMaxDynamicSharedMemorySize, GEMM_SMEM);
    }
    const size_t WSZ = (size_t)D_MODEL * D_MODEL;

    prepass_kernel<<<dim3(32, 32, 5), 256>>>(x, Wq, Wk, Wv, Wo);

    qkv_gemm_kernel<<<dim3(D_MODEL / 128, MROWS / 128, 3), 128, GEMM_SMEM>>>(
        wt_base, bq, bk, bv);

    flash_kernel<<<dim3(SEQ / 64, BHN), 128>>>();

    out_gemm_kernel<<<dim3(D_MODEL / 128, MROWS / 128), 128, GEMM_SMEM>>>(
        wt_base + 3 * WSZ, bo, (float*)d_out);
}

// round 17
// speedup vs baseline: 1.0682x; 1.0682x over previous
#include <cuda_runtime.h>
#include <cuda_fp16.h>
#include <math.h>
#include <stdint.h>

#define D_MODEL 1024
#define NHEAD   16
#define DH      64
#define BATCH   2
#define SEQ     2048
#define MROWS   (BATCH*SEQ)   // 4096
#define BHN     (BATCH*NHEAD) // 32

// Scratch (allocation-free): fp16 buffers.
__device__ __align__(16) __half g_Qh[BHN * SEQ * DH];
__device__ __align__(16) __half g_Kh[BHN * SEQ * DH];
__device__ __align__(16) __half g_Vh[BHN * SEQ * DH];
__device__ __align__(16) __half g_Oh[BHN * SEQ * DH];
__device__ __align__(16) __half g_xh[MROWS * D_MODEL];
__device__ __align__(16) __half g_Wt[4][D_MODEL * D_MODEL];  // [n][k] fp16

// ---------------------------------------------------------------------------
// helpers
// ---------------------------------------------------------------------------
__device__ __forceinline__ uint32_t pack2(float a, float b) {
    __half2 h = __floats2half2_rn(a, b);
    return *reinterpret_cast<uint32_t*>(&h);
}
__device__ __forceinline__ uint32_t h2exp2(uint32_t x) {
    uint32_t r;
    asm volatile("ex2.approx.f16x2 %0, %1;" : "=r"(r) : "r"(x));
    return r;
}
__device__ __forceinline__ uint32_t smem_u32(const void* p) {
    uint32_t r;
    asm("{ .reg .u64 t; cvta.to.shared.u64 t, %1; cvt.u32.u64 %0, t; }"
        : "=r"(r) : "l"(p));
    return r;
}
__device__ __forceinline__ void mma16(float* c, const uint32_t* a,
                                      uint32_t b0, uint32_t b1) {
    asm volatile(
        "mma.sync.aligned.m16n8k16.row.col.f32.f16.f16.f32 "
        "{%0,%1,%2,%3}, {%4,%5,%6,%7}, {%8,%9}, {%0,%1,%2,%3};"
        : "+f"(c[0]), "+f"(c[1]), "+f"(c[2]), "+f"(c[3])
        : "r"(a[0]), "r"(a[1]), "r"(a[2]), "r"(a[3]), "r"(b0), "r"(b1));
}
__device__ __forceinline__ void ldm_x4(uint32_t* r, uint32_t addr) {
    asm volatile("ldmatrix.sync.aligned.m8n8.x4.shared.b16 {%0,%1,%2,%3}, [%4];"
        : "=r"(r[0]), "=r"(r[1]), "=r"(r[2]), "=r"(r[3]) : "r"(addr));
}
__device__ __forceinline__ void ldm_x4_t(uint32_t* r, uint32_t addr) {
    asm volatile("ldmatrix.sync.aligned.m8n8.x4.trans.shared.b16 {%0,%1,%2,%3}, [%4];"
        : "=r"(r[0]), "=r"(r[1]), "=r"(r[2]), "=r"(r[3]) : "r"(addr));
}
__device__ __forceinline__ void cpa16(uint32_t dst, const void* src) {
    asm volatile("cp.async.cg.shared.global [%0], [%1], 16;"
                 :: "r"(dst), "l"(src) : "memory");
}
#define CPA_COMMIT() asm volatile("cp.async.commit_group;" ::: "memory")
#define CPA_WAIT0()  asm volatile("cp.async.wait_group 0;" ::: "memory")
#define CPA_WAIT1()  asm volatile("cp.async.wait_group 1;" ::: "memory")
#define CPA_WAIT2()  asm volatile("cp.async.wait_group 2;" ::: "memory")

// ---------------------------------------------------------------------------
// Fused pre-pass: z<4 -> W[z] transpose to fp16 [n][k]; z==4 -> x to fp16.
// grid (32, 32, 5), block 256.
// ---------------------------------------------------------------------------
__global__ __launch_bounds__(256) void prepass_kernel(
    const float* __restrict__ x,
    const float* __restrict__ W0, const float* __restrict__ W1,
    const float* __restrict__ W2, const float* __restrict__ W3)
{
    const int z = blockIdx.z;
    if (z == 4) {
        int bid = blockIdx.y * 32 + blockIdx.x;
        #pragma unroll
        for (int j = 0; j < 4; j++) {
            int idx = (bid * 4 + j) * 256 + threadIdx.x;
            float4 v = *(const float4*)(x + (size_t)idx * 4);
            *(uint2*)(g_xh + (size_t)idx * 4) =
                make_uint2(pack2(v.x, v.y), pack2(v.z, v.w));
        }
        return;
    }
    __shared__ float tile[32][33];
    const float* W = (z == 0) ? W0 : (z == 1) ? W1 : (z == 2) ? W2 : W3;
    const int tx = threadIdx.x & 31, ty = threadIdx.x >> 5;  // (32, 8)
    const int k0 = blockIdx.y * 32, n0 = blockIdx.x * 32;
    #pragma unroll
    for (int j = 0; j < 4; j++)
        tile[ty + 8 * j][tx] = W[(size_t)(k0 + ty + 8 * j) * D_MODEL + n0 + tx];
    __syncthreads();
    __half* Wt = g_Wt[z];
    #pragma unroll
    for (int jj = 0; jj < 2; jj++) {
        int w_ = threadIdx.x + 256 * jj;   // 0..511
        int n = w_ >> 4, c = w_ & 15;
        uint32_t u = pack2(tile[2 * c][n], tile[2 * c + 1][n]);
        *(uint32_t*)(Wt + (size_t)(n0 + n) * D_MODEL + k0 + 2 * c) = u;
    }
}

// ---------------------------------------------------------------------------
// GEMM geometry: CTA 128x128, 128 threads (4 warps, 2x2), warp tile 64x64.
// BK=32, 4-stage cp.async pipeline (prefetch distance 3), 2 CTAs/SM.
// ---------------------------------------------------------------------------
#define BK   32
#define NS   (D_MODEL / BK)        // 32
#define GST  20                     // u32 words per smem row
#define BUFW (256 * GST)            // A(128) + W(128) rows per buffer
#define GEMM_SMEM (4 * BUFW * 4)    // 81920 B dynamic

struct GemmCtx {
    int m0w, n0w;
    int lrow, a_roff, a_coff, b_roff, b_coff;
};
__device__ __forceinline__ void gemm_stage(const GemmCtx& c, uint32_t ab,
                                           float acc[4][8][4]) {
    const uint32_t wb = ab + 128 * GST * 4;
    #pragma unroll
    for (int ks = 0; ks < 2; ks++) {
        const int k0w = ks * 8;
        uint32_t a[4][4], b[4][4];
        #pragma unroll
        for (int mt = 0; mt < 4; mt++)
            ldm_x4(a[mt], ab + ((c.m0w + mt * 16 + c.a_roff + c.lrow) * GST
                                + k0w + c.a_coff) * 4);
        #pragma unroll
        for (int np = 0; np < 4; np++)
            ldm_x4(b[np], wb + ((c.n0w + np * 16 + c.b_roff + c.lrow) * GST
                                + k0w + c.b_coff) * 4);
        #pragma unroll
        for (int nt = 0; nt < 8; nt++) {
            uint32_t b0 = b[nt >> 1][(nt & 1) * 2];
            uint32_t b1 = b[nt >> 1][(nt & 1) * 2 + 1];
            #pragma unroll
            for (int mt = 0; mt < 4; mt++)
                mma16(acc[mt][nt], a[mt], b0, b1);
        }
    }
}

// stage wait ladder: group s must have completed
#define GEMM_WAIT(s) do { \
    if ((s) + 2 < NS) CPA_WAIT2(); \
    else if ((s) + 1 < NS) CPA_WAIT1(); \
    else CPA_WAIT0(); \
} while (0)

// ---------------------------------------------------------------------------
// Fused QKV projection GEMM. grid (8, 32, 3), block 128, 2 CTAs/SM.
// ---------------------------------------------------------------------------
__global__ __launch_bounds__(128, 2) void qkv_gemm_kernel(
    const __half* __restrict__ wt_base,
    const float* __restrict__ bq, const float* __restrict__ bk,
    const float* __restrict__ bv)
{
    extern __shared__ uint32_t sm[];

    const int tid  = threadIdx.x;
    const int w    = tid >> 5, lane = tid & 31;
    const int g    = lane >> 2, t = lane & 3;
    const int bm   = blockIdx.y * 128, bn = blockIdx.x * 128;
    const int bb   = bm >> 11;
    const int z    = blockIdx.z;

    const __half* Wt = wt_base + (size_t)z * D_MODEL * D_MODEL;
    const float* bias = (z == 0) ? bq : (z == 1) ? bk : bv;
    const float alpha = (z == 0) ? 0.125f * 1.4426950408889634f : 1.0f;

    GemmCtx c;
    c.m0w = (w >> 1) * 64; c.n0w = (w & 1) * 64;
    c.lrow = lane & 7;
    c.a_roff = ((lane >> 3) & 1) * 8;
    c.a_coff = (lane >> 4) * 4;
    c.b_roff = (lane >> 4) * 8;
    c.b_coff = ((lane >> 3) & 1) * 4;

    const uint32_t smb = smem_u32(sm);

    auto issue = [&](int kt, int buf) {
        uint32_t dst = smb + buf * (BUFW * 4);
        #pragma unroll
        for (int i = 0; i < 4; i++) {
            int idx = tid + 128 * i;
            int row = idx >> 2, seg = idx & 3;
            cpa16(dst + (row * GST + seg * 4) * 4,
                  g_xh + (size_t)(bm + row) * D_MODEL + kt + seg * 8);
            cpa16(dst + ((128 + row) * GST + seg * 4) * 4,
                  Wt + (size_t)(bn + row) * D_MODEL + kt + seg * 8);
        }
        CPA_COMMIT();
    };

    issue(0, 0);
    issue(BK, 1);
    issue(2 * BK, 2);

    float acc[4][8][4] = {};

    #pragma unroll 1
    for (int s = 0; s < NS; s++) {
        GEMM_WAIT(s);
        __syncthreads();
        if (s + 3 < NS) issue((s + 3) * BK, (s + 3) & 3);
        gemm_stage(c, smb + (s & 3) * (BUFW * 4), acc);
    }

    __half* outp = (z == 0) ? g_Qh : (z == 1) ? g_Kh : g_Vh;
    #pragma unroll
    for (int mt = 0; mt < 4; mt++) {
        #pragma unroll
        for (int nt = 0; nt < 8; nt++) {
            int rl = c.m0w + mt * 16 + g;
            int cl = c.n0w + nt * 8 + t * 2;
            float2 bv2 = *(const float2*)&bias[bn + cl];
            float v00 = (acc[mt][nt][0] + bv2.x) * alpha;
            float v01 = (acc[mt][nt][1] + bv2.y) * alpha;
            float v10 = (acc[mt][nt][2] + bv2.x) * alpha;
            float v11 = (acc[mt][nt][3] + bv2.y) * alpha;
            int col = bn + cl;
            int h = col >> 6, d = col & 63;
            int t0r = (bm + rl) & (SEQ - 1);
            __half* ob = outp + ((size_t)(bb * NHEAD + h)) * SEQ * DH;
            *(uint32_t*)&ob[(size_t)t0r * DH + d] = pack2(v00, v01);
            *(uint32_t*)&ob[(size_t)(t0r + 8) * DH + d] = pack2(v10, v11);
        }
    }
}

// ---------------------------------------------------------------------------
// Output GEMM: d_out = concat(O) @ Wo + bo. grid (8, 32), block 128.
// ---------------------------------------------------------------------------
__global__ __launch_bounds__(128, 2) void out_gemm_kernel(
    const __half* __restrict__ Wt, const float* __restrict__ bias,
    float* __restrict__ Cout)
{
    extern __shared__ uint32_t sm[];

    const int tid  = threadIdx.x;
    const int w    = tid >> 5, lane = tid & 31;
    const int g    = lane >> 2, t = lane & 3;
    const int bm   = blockIdx.y * 128, bn = blockIdx.x * 128;
    const int bb   = bm >> 11;

    GemmCtx c;
    c.m0w = (w >> 1) * 64; c.n0w = (w & 1) * 64;
    c.lrow = lane & 7;
    c.a_roff = ((lane >> 3) & 1) * 8;
    c.a_coff = (lane >> 4) * 4;
    c.b_roff = (lane >> 4) * 8;
    c.b_coff = ((lane >> 3) & 1) * 4;

    const uint32_t smb = smem_u32(sm);

    auto issue = [&](int kt, int buf) {
        uint32_t dst = smb + buf * (BUFW * 4);
        const int h = kt >> 6, d0 = kt & 63;
        #pragma unroll
        for (int i = 0; i < 4; i++) {
            int idx = tid + 128 * i;
            int row = idx >> 2, seg = idx & 3;
            int tt = (bm + row) & (SEQ - 1);
            cpa16(dst + (row * GST + seg * 4) * 4,
                  g_Oh + (((size_t)(bb * NHEAD + h)) * SEQ + tt) * DH
                  + d0 + seg * 8);
            cpa16(dst + ((128 + row) * GST + seg * 4) * 4,
                  Wt + (size_t)(bn + row) * D_MODEL + kt + seg * 8);
        }
        CPA_COMMIT();
    };

    issue(0, 0);
    issue(BK, 1);
    issue(2 * BK, 2);

    float acc[4][8][4] = {};

    #pragma unroll 1
    for (int s = 0; s < NS; s++) {
        GEMM_WAIT(s);
        __syncthreads();
        if (s + 3 < NS) issue((s + 3) * BK, (s + 3) & 3);
        gemm_stage(c, smb + (s & 3) * (BUFW * 4), acc);
    }

    #pragma unroll
    for (int mt = 0; mt < 4; mt++) {
        #pragma unroll
        for (int nt = 0; nt < 8; nt++) {
            int rl = c.m0w + mt * 16 + g;
            int cl = c.n0w + nt * 8 + t * 2;
            float2 bv2 = *(const float2*)&bias[bn + cl];
            *(float2*)&Cout[(size_t)(bm + rl) * D_MODEL + bn + cl] =
                make_float2(acc[mt][nt][0] + bv2.x, acc[mt][nt][1] + bv2.y);
            *(float2*)&Cout[(size_t)(bm + rl + 8) * D_MODEL + bn + cl] =
                make_float2(acc[mt][nt][2] + bv2.x, acc[mt][nt][3] + bv2.y);
        }
    }
}

// ---------------------------------------------------------------------------
// Flash attention (R10 config — measured best). CTA = 128 threads (4 warps)
// x 64 queries; 4 CTAs/SM. cp.async double-buffered 64-key tiles;
// ex2.approx.f16x2 softmax; row-sums l via MMA against all-ones B fragment.
// ---------------------------------------------------------------------------
#define FST 36
#define KVW (64 * FST)
#define H2_ONES 0x3C003C00u

__global__ __launch_bounds__(128, 4) void flash_kernel()
{
    __shared__ uint32_t Ks[2][KVW];
    __shared__ uint32_t Vs[2][KVW];

    const int tid = threadIdx.x;
    const int w = tid >> 5, lane = tid & 31;
    const int g = lane >> 2, t = lane & 3;
    const int bh = blockIdx.y;
    const int q0 = blockIdx.x * 64;

    const __half* Qp = g_Qh + ((size_t)bh * SEQ + q0) * DH;
    const __half* Kp = g_Kh + (size_t)bh * SEQ * DH;
    const __half* Vp = g_Vh + (size_t)bh * SEQ * DH;

    const int lr = w * 16 + g;

    uint32_t qf[4][4];
    #pragma unroll
    for (int s = 0; s < 4; s++) {
        qf[s][0] = *(const uint32_t*)(Qp + (size_t)lr * DH + s * 16 + 2 * t);
        qf[s][1] = *(const uint32_t*)(Qp + (size_t)(lr + 8) * DH + s * 16 + 2 * t);
        qf[s][2] = *(const uint32_t*)(Qp + (size_t)lr * DH + s * 16 + 8 + 2 * t);
        qf[s][3] = *(const uint32_t*)(Qp + (size_t)(lr + 8) * DH + s * 16 + 8 + 2 * t);
    }

    const uint32_t ksb = smem_u32(Ks), vsb = smem_u32(Vs);
    const int lrow = lane & 7;
    const uint32_t k_lane = ksb + (lrow * FST + (lane >> 3) * 4) * 4;
    const uint32_t v_lane = vsb + ((((lane >> 3) & 1) * 8 + lrow) * FST
                                   + (lane >> 4) * 4) * 4;

    auto issueKV = [&](int kt, int buf) {
        const uint32_t koff = buf * (KVW * 4);
        #pragma unroll
        for (int i = 0; i < 4; i++) {
            int idx = i * 128 + tid;
            int row = idx >> 3, seg = idx & 7;
            cpa16(ksb + koff + (row * FST + seg * 4) * 4,
                  Kp + (size_t)(kt + row) * DH + seg * 8);
            cpa16(vsb + koff + (row * FST + seg * 4) * 4,
                  Vp + (size_t)(kt + row) * DH + seg * 8);
        }
        CPA_COMMIT();
    };

    issueKV(0, 0);

    float o[8][4] = {};
    float lsum[4] = {};
    float m0 = -INFINITY, m1 = -INFINITY;

    #pragma unroll 1
    for (int it = 0; it < SEQ / 64; it++) {
        const int buf = it & 1;
        CPA_WAIT0();
        __syncthreads();
        if (it + 1 < SEQ / 64) issueKV((it + 1) * 64, buf ^ 1);

        const uint32_t kl = k_lane + buf * (KVW * 4);
        const uint32_t vl = v_lane + buf * (KVW * 4);

        float s_[8][4] = {};
        #pragma unroll
        for (int nt = 0; nt < 8; nt++) {
            uint32_t kb[4], kb2[4];
            uint32_t base = kl + nt * 8 * (FST * 4);
            ldm_x4(kb,  base);
            ldm_x4(kb2, base + 16 * 4);
            mma16(s_[nt], qf[0], kb[0],  kb[1]);
            mma16(s_[nt], qf[1], kb[2],  kb[3]);
            mma16(s_[nt], qf[2], kb2[0], kb2[1]);
            mma16(s_[nt], qf[3], kb2[2], kb2[3]);
        }

        float mx0 = -INFINITY, mx1 = -INFINITY;
        #pragma unroll
        for (int nt = 0; nt < 8; nt++) {
            mx0 = fmaxf(mx0, fmaxf(s_[nt][0], s_[nt][1]));
            mx1 = fmaxf(mx1, fmaxf(s_[nt][2], s_[nt][3]));
        }
        mx0 = fmaxf(mx0, __shfl_xor_sync(0xffffffffu, mx0, 1));
        mx0 = fmaxf(mx0, __shfl_xor_sync(0xffffffffu, mx0, 2));
        mx1 = fmaxf(mx1, __shfl_xor_sync(0xffffffffu, mx1, 1));
        mx1 = fmaxf(mx1, __shfl_xor_sync(0xffffffffu, mx1, 2));

        float mn0 = fmaxf(m0, mx0), mn1 = fmaxf(m1, mx1);
        float c0 = exp2f(m0 - mn0), c1 = exp2f(m1 - mn1);
        m0 = mn0; m1 = mn1;

        uint32_t pf[4][4];
        #pragma unroll
        for (int s = 0; s < 4; s++) {
            pf[s][0] = h2exp2(pack2(s_[2 * s][0] - mn0,     s_[2 * s][1] - mn0));
            pf[s][1] = h2exp2(pack2(s_[2 * s][2] - mn1,     s_[2 * s][3] - mn1));
            pf[s][2] = h2exp2(pack2(s_[2 * s + 1][0] - mn0, s_[2 * s + 1][1] - mn0));
            pf[s][3] = h2exp2(pack2(s_[2 * s + 1][2] - mn1, s_[2 * s + 1][3] - mn1));
        }

        #pragma unroll
        for (int nt = 0; nt < 8; nt++) {
            o[nt][0] *= c0; o[nt][1] *= c0;
            o[nt][2] *= c1; o[nt][3] *= c1;
        }
        lsum[0] *= c0; lsum[1] *= c0; lsum[2] *= c1; lsum[3] *= c1;

        #pragma unroll
        for (int s = 0; s < 4; s++)
            mma16(lsum, pf[s], H2_ONES, H2_ONES);

        #pragma unroll
        for (int s = 0; s < 4; s++) {
            uint32_t base = vl + s * 16 * (FST * 4);
            #pragma unroll
            for (int np = 0; np < 4; np++) {
                uint32_t vb[4];
                ldm_x4_t(vb, base + np * 8 * 4);
                mma16(o[2 * np],     pf[s], vb[0], vb[1]);
                mma16(o[2 * np + 1], pf[s], vb[2], vb[3]);
            }
        }
    }

    float inv0 = 1.0f / lsum[0], inv1 = 1.0f / lsum[2];
    __half* Op = g_Oh + ((size_t)bh * SEQ + q0) * DH;
    #pragma unroll
    for (int nt = 0; nt < 8; nt++) {
        int col = nt * 8 + t * 2;
        *(uint32_t*)&Op[(size_t)lr * DH + col] =
            pack2(o[nt][0] * inv0, o[nt][1] * inv0);
        *(uint32_t*)&Op[(size_t)(lr + 8) * DH + col] =
            pack2(o[nt][2] * inv1, o[nt][3] * inv1);
    }
}

// ---------------------------------------------------------------------------
extern "C" void kernel_launch(void* const* d_in, const int* in_sizes, int n_in,
                              void* d_out, int out_size)
{
    const float* x  = (const float*)d_in[0];
    const float* Wq = (const float*)d_in[1];
    const float* bq = (const float*)d_in[2];
    const float* Wk = (const float*)d_in[3];
    const float* bk = (const float*)d_in[4];
    const float* Wv = (const float*)d_in[5];
    const float* bv = (const float*)d_in[6];
    const float* Wo = (const float*)d_in[7];
    const float* bo = (const float*)d_in[8];
    (void)in_sizes; (void)n_in; (void)out_size;

    static __half* wt_base = nullptr;
    if (!wt_base) {
        void* p = nullptr;
        cudaGetSymbolAddress(&p, g_Wt);
        wt_base = (__half*)p;
        cudaFuncSetAttribute(qkv_gemm_kernel,
            cudaFuncAttributeMaxDynamicSharedMemorySize, GEMM_SMEM);
        cudaFuncSetAttribute(out_gemm_kernel,
            cudaFuncAttributeMaxDynamicSharedMemorySize, GEMM_SMEM);
    }
    const size_t WSZ = (size_t)D_MODEL * D_MODEL;

    prepass_kernel<<<dim3(32, 32, 5), 256>>>(x, Wq, Wk, Wv, Wo);

    qkv_gemm_kernel<<<dim3(D_MODEL / 128, MROWS / 128, 3), 128, GEMM_SMEM>>>(
        wt_base, bq, bk, bv);

    flash_kernel<<<dim3(SEQ / 64, BHN), 128>>>();

    out_gemm_kernel<<<dim3(D_MODEL / 128, MROWS / 128), 128, GEMM_SMEM>>>(
        wt_base + 3 * WSZ, bo, (float*)d_out);
}